// round 6
// baseline (speedup 1.0000x reference)
#include <cuda_runtime.h>
#include <cuda_fp16.h>
#include <cstdint>
#include <math.h>

#define T_TOK 2048
#define DM    2048
#define FM    8192
#define EM    4
#define KM    2

// ---------------- scratch ----------------------------------------------------
__device__ int    g_count[EM];
__device__ int    g_bucket[EM * T_TOK];
__device__ float  g_gate[EM * T_TOK];
__device__ int    g_slot[T_TOK * KM];
__device__ __half g_xh[T_TOK * DM];                  // x in half
__device__ __half g_Wgh[(size_t)EM * FM * DM];       // Wg^T [E][F][D] half
__device__ __half g_Wuh[(size_t)EM * FM * DM];       // Wu^T [E][F][D] half
__device__ __half g_Wdh[(size_t)EM * DM * FM];       // Wd^T [E][D][F] half
__device__ __half g_Hh[(size_t)EM * T_TOK * FM];     // hidden in half
__device__ float  g_Y[(size_t)EM * T_TOK * DM];      // per-slot output fp32

// ---------------- helpers ----------------------------------------------------
__device__ __forceinline__ void mma_f16(float* c, const uint32_t* a, const uint32_t* b) {
    asm volatile(
        "mma.sync.aligned.m16n8k16.row.col.f32.f16.f16.f32 "
        "{%0,%1,%2,%3}, {%4,%5,%6,%7}, {%8,%9}, {%0,%1,%2,%3};\n"
        : "+f"(c[0]), "+f"(c[1]), "+f"(c[2]), "+f"(c[3])
        : "r"(a[0]), "r"(a[1]), "r"(a[2]), "r"(a[3]), "r"(b[0]), "r"(b[1]));
}

__device__ __forceinline__ float silu_f(float x) { return x / (1.0f + expf(-x)); }

__device__ __forceinline__ uint32_t smem_u32(const void* p) {
    uint32_t a;
    asm("{ .reg .u64 t; cvta.to.shared.u64 t, %1; cvt.u32.u64 %0, t; }" : "=r"(a) : "l"(p));
    return a;
}

__device__ __forceinline__ void cpa16(uint32_t dst, const void* src, uint32_t sz) {
    asm volatile("cp.async.cg.shared.global [%0], [%1], 16, %2;\n"
                 :: "r"(dst), "l"(src), "r"(sz));
}
#define CP_COMMIT() asm volatile("cp.async.commit_group;\n" ::: "memory")
#define CP_WAIT1()  asm volatile("cp.async.wait_group 1;\n" ::: "memory")

// ---------------- prep kernels ------------------------------------------------
__global__ void init_counts_kernel() { if (threadIdx.x < EM) g_count[threadIdx.x] = 0; }

__global__ void cvt_x_kernel(const float* __restrict__ x) {
    const int i = blockIdx.x * 256 + threadIdx.x;      // over T*DM/4
    float4 v = ((const float4*)x)[i];
    __half2 h0 = __floats2half2_rn(v.x, v.y);
    __half2 h1 = __floats2half2_rn(v.z, v.w);
    ((__half2*)g_xh)[i * 2]     = h0;
    ((__half2*)g_xh)[i * 2 + 1] = h1;
}

// dst[e][c][r] = half(src[e][r][c]); which: 0->Wgh 1->Wuh 2->Wdh
__global__ void transpose_cvt_kernel(const float* __restrict__ src, int which, int R, int C) {
    __shared__ float t[32][33];
    const int e = blockIdx.z, c0 = blockIdx.x * 32, r0 = blockIdx.y * 32;
    __half* dst = (which == 0) ? g_Wgh : (which == 1) ? g_Wuh : g_Wdh;
    const float* s = src + (size_t)e * R * C;
    __half* d = dst + (size_t)e * R * C;
    const int x = threadIdx.x;
#pragma unroll
    for (int yy = threadIdx.y; yy < 32; yy += 8)
        t[yy][x] = s[(size_t)(r0 + yy) * C + c0 + x];
    __syncthreads();
#pragma unroll
    for (int yy = threadIdx.y; yy < 32; yy += 8)
        d[(size_t)(c0 + yy) * R + r0 + x] = __float2half_rn(t[x][yy]);
}

__global__ void router_kernel(const float* __restrict__ x, const float* __restrict__ Wr) {
    const int t = blockIdx.x, tid = threadIdx.x;
    const float* xr = x + (size_t)t * DM;
    float acc[EM] = {0.f, 0.f, 0.f, 0.f};
    for (int d = tid; d < DM; d += 128) {
        const float xv = xr[d];
#pragma unroll
        for (int e = 0; e < EM; e++) acc[e] += xv * Wr[d * EM + e];
    }
    __shared__ float sred[EM][128];
#pragma unroll
    for (int e = 0; e < EM; e++) sred[e][tid] = acc[e];
    __syncthreads();
    for (int s = 64; s > 0; s >>= 1) {
        if (tid < s) {
#pragma unroll
            for (int e = 0; e < EM; e++) sred[e][tid] += sred[e][tid + s];
        }
        __syncthreads();
    }
    if (tid == 0) {
        float l[EM];
#pragma unroll
        for (int e = 0; e < EM; e++) l[e] = sred[e][0];
        float mx = l[0];
#pragma unroll
        for (int e = 1; e < EM; e++) mx = fmaxf(mx, l[e]);
        float p[EM], sum = 0.f;
#pragma unroll
        for (int e = 0; e < EM; e++) { p[e] = expf(l[e] - mx); sum += p[e]; }
        const float inv = 1.0f / sum;
#pragma unroll
        for (int e = 0; e < EM; e++) p[e] *= inv;
        int e0 = 0;
#pragma unroll
        for (int e = 1; e < EM; e++) if (p[e] > p[e0]) e0 = e;
        int e1 = -1;
#pragma unroll
        for (int e = 0; e < EM; e++) {
            if (e == e0) continue;
            if (e1 < 0 || p[e] > p[e1]) e1 = e;
        }
        int s0 = atomicAdd(&g_count[e0], 1);
        g_bucket[e0 * T_TOK + s0] = t; g_gate[e0 * T_TOK + s0] = p[e0];
        g_slot[t * KM + 0] = e0 * T_TOK + s0;
        int s1 = atomicAdd(&g_count[e1], 1);
        g_bucket[e1 * T_TOK + s1] = t; g_gate[e1 * T_TOK + s1] = p[e1];
        g_slot[t * KM + 1] = e1 * T_TOK + s1;
    }
}

// =============== GEMM1: H = silu(x Wg) * (x Wu), fp16 MMA =====================
// Block 128M x 64F dual. 8 warps: wm=warp&3 (4x32M), wn=warp>>2 (2x32F).
// A [128][32] half (pitch 40), Bg/Bu [64 f][32 k] half (pitch 40) — K-contiguous.
#define G1_AP 40                          // halves
#define G1_BP 40
#define G1_AB (128 * G1_AP * 2)           // 10240 B
#define G1_BB (64 * G1_BP * 2)            // 5120 B
#define G1_STAGE (G1_AB + 2 * G1_BB)      // 20480
#define G1_ROWS  (3 * G1_STAGE)           // 61440
#define G1_SMEM  (G1_ROWS + 512)

__global__ __launch_bounds__(256, 2)
void gemm1_kernel() {
    extern __shared__ char sm[];
    const int e   = blockIdx.z;
    const int cnt = g_count[e];
    const int m0  = blockIdx.x * 128;
    if (m0 >= cnt) return;
    const int f0  = blockIdx.y * 64;

    const int tid = threadIdx.x, warp = tid >> 5, lane = tid & 31;
    const int wm = warp & 3, wn = warp >> 2;
    const int q = lane >> 2, r2 = lane & 3;
    const uint32_t sb = smem_u32(sm);
    int* rows = (int*)(sm + G1_ROWS);

    if (tid < 128) {
        const int m = m0 + tid;
        rows[tid] = (m < cnt) ? g_bucket[e * T_TOK + m] : -1;
    }
    __syncthreads();

    const __half* Wge = g_Wgh + (size_t)e * FM * DM + (size_t)f0 * DM;
    const __half* Wue = g_Wuh + (size_t)e * FM * DM + (size_t)f0 * DM;

    auto load_tile = [&](int s, int kt) {
        const int k0 = kt * 32;                        // halves
        const uint32_t ab = sb + s * G1_STAGE;
#pragma unroll
        for (int p = 0; p < 2; p++) {                  // A: 128 rows x 2 chunks
            const int idx = tid + p * 256;
            const int rr = idx >> 2, c = idx & 3;      // rr 0..127, c 0..3 -> but 2 chunks? fix: 128*2=256... 
            (void)rr; (void)c;
        }
        // A: 128 rows, 64B/row = 4 chunks -> 512 chunks, 2 per thread
#pragma unroll
        for (int p = 0; p < 2; p++) {
            const int idx = tid + p * 256;
            const int rr = idx >> 2, c = idx & 3;
            const int tok = rows[rr];
            const __half* src = (tok >= 0) ? (g_xh + (size_t)tok * DM + k0 + c * 8) : g_xh;
            cpa16(ab + rr * (G1_AP * 2) + c * 16, src, (tok >= 0) ? 16u : 0u);
        }
        {   // Bg: 64 rows x 4 chunks = 256, 1 per thread
            const int fr = tid >> 2, c = tid & 3;
            cpa16(ab + G1_AB + fr * (G1_BP * 2) + c * 16,
                  Wge + (size_t)fr * DM + k0 + c * 8, 16);
        }
        {   // Bu
            const int fr = tid >> 2, c = tid & 3;
            cpa16(ab + G1_AB + G1_BB + fr * (G1_BP * 2) + c * 16,
                  Wue + (size_t)fr * DM + k0 + c * 8, 16);
        }
    };

    float accG[2][4][4], accU[2][4][4];
#pragma unroll
    for (int mi = 0; mi < 2; mi++)
#pragma unroll
        for (int ni = 0; ni < 4; ni++)
#pragma unroll
            for (int j = 0; j < 4; j++) { accG[mi][ni][j] = 0.f; accU[mi][ni][j] = 0.f; }

    const int KT = DM / 32;   // 64
    load_tile(0, 0); CP_COMMIT();
    load_tile(1, 1); CP_COMMIT();

    for (int kt = 0; kt < KT; kt++) {
        CP_WAIT1();
        __syncthreads();
        if (kt + 2 < KT) load_tile((kt + 2) % 3, kt + 2);

        const uint32_t* As = (const uint32_t*)(sm + (kt % 3) * G1_STAGE);  // half2 units
        const uint32_t* Bg = As + 128 * (G1_AP / 2);
        const uint32_t* Bu = Bg + 64 * (G1_BP / 2);
        const int AP2 = G1_AP / 2, BP2 = G1_BP / 2;

#pragma unroll
        for (int k16 = 0; k16 < 2; k16++) {
            const int kk2 = k16 * 8;                   // half2 index of k base
            uint32_t a[2][4];
#pragma unroll
            for (int mi = 0; mi < 2; mi++) {
                const int mr = wm * 32 + mi * 16 + q;
                a[mi][0] = As[mr * AP2 + kk2 + r2];
                a[mi][1] = As[(mr + 8) * AP2 + kk2 + r2];
                a[mi][2] = As[mr * AP2 + kk2 + r2 + 4];
                a[mi][3] = As[(mr + 8) * AP2 + kk2 + r2 + 4];
            }
#pragma unroll
            for (int ni = 0; ni < 4; ni++) {
                const int nc = wn * 32 + ni * 8 + q;
                uint32_t bg[2] = { Bg[nc * BP2 + kk2 + r2], Bg[nc * BP2 + kk2 + r2 + 4] };
                uint32_t bu[2] = { Bu[nc * BP2 + kk2 + r2], Bu[nc * BP2 + kk2 + r2 + 4] };
#pragma unroll
                for (int mi = 0; mi < 2; mi++) {
                    mma_f16(accG[mi][ni], a[mi], bg);
                    mma_f16(accU[mi][ni], a[mi], bu);
                }
            }
        }
        CP_COMMIT();
    }

    // epilogue: H = half(silu(g)*u)
    const int rb = m0 + wm * 32;
#pragma unroll
    for (int mi = 0; mi < 2; mi++) {
        const int r0 = rb + mi * 16 + q;
#pragma unroll
        for (int ni = 0; ni < 4; ni++) {
            const int col = f0 + wn * 32 + ni * 8 + r2 * 2;
            __half* p0 = g_Hh + ((size_t)(e * T_TOK) + r0) * FM + col;
            __half* p1 = p0 + (size_t)8 * FM;
            *(__half2*)p0 = __floats2half2_rn(silu_f(accG[mi][ni][0]) * accU[mi][ni][0],
                                              silu_f(accG[mi][ni][1]) * accU[mi][ni][1]);
            *(__half2*)p1 = __floats2half2_rn(silu_f(accG[mi][ni][2]) * accU[mi][ni][2],
                                              silu_f(accG[mi][ni][3]) * accU[mi][ni][3]);
        }
    }
}

// =============== GEMM2: Y = H Wd, fp16 MMA ====================================
// Block 128M x 128N. 8 warps: wm=warp&1 (2x64M), wn=warp>>1 (4x32N).
// A [128][32] half (pitch 40), B [128 n][32 k] half (pitch 40) — K-contiguous.
#define G2_AP 40
#define G2_BP 40
#define G2_AB (128 * G2_AP * 2)           // 10240
#define G2_BB (128 * G2_BP * 2)           // 10240
#define G2_STAGE (G2_AB + G2_BB)          // 20480
#define G2_SMEM  (3 * G2_STAGE)           // 61440

__global__ __launch_bounds__(256, 2)
void gemm2_kernel() {
    extern __shared__ char sm[];
    const int e   = blockIdx.z;
    const int cnt = g_count[e];
    const int m0  = blockIdx.x * 128;
    if (m0 >= cnt) return;
    const int d0  = blockIdx.y * 128;

    const int tid = threadIdx.x, warp = tid >> 5, lane = tid & 31;
    const int wm = warp & 1, wn = warp >> 1;
    const int q = lane >> 2, r2 = lane & 3;
    const uint32_t sb = smem_u32(sm);

    const __half* Hb  = g_Hh + (size_t)(e * T_TOK + m0) * FM;
    const __half* Wde = g_Wdh + (size_t)e * DM * FM + (size_t)d0 * FM;

    auto load_tile = [&](int s, int kt) {
        const int k0 = kt * 32;
        const uint32_t ab = sb + s * G2_STAGE;
#pragma unroll
        for (int p = 0; p < 2; p++) {                  // A: 512 chunks
            const int idx = tid + p * 256;
            const int rr = idx >> 2, c = idx & 3;
            cpa16(ab + rr * (G2_AP * 2) + c * 16, Hb + (size_t)rr * FM + k0 + c * 8, 16);
        }
#pragma unroll
        for (int p = 0; p < 2; p++) {                  // B: 512 chunks
            const int idx = tid + p * 256;
            const int nr = idx >> 2, c = idx & 3;
            cpa16(ab + G2_AB + nr * (G2_BP * 2) + c * 16,
                  Wde + (size_t)nr * FM + k0 + c * 8, 16);
        }
    };

    float acc[4][4][4];
#pragma unroll
    for (int mi = 0; mi < 4; mi++)
#pragma unroll
        for (int ni = 0; ni < 4; ni++)
#pragma unroll
            for (int j = 0; j < 4; j++) acc[mi][ni][j] = 0.f;

    const int KT = FM / 32;   // 256
    load_tile(0, 0); CP_COMMIT();
    load_tile(1, 1); CP_COMMIT();

    for (int kt = 0; kt < KT; kt++) {
        CP_WAIT1();
        __syncthreads();
        if (kt + 2 < KT) load_tile((kt + 2) % 3, kt + 2);

        const uint32_t* As = (const uint32_t*)(sm + (kt % 3) * G2_STAGE);
        const uint32_t* Bs = As + 128 * (G2_AP / 2);
        const int AP2 = G2_AP / 2, BP2 = G2_BP / 2;

#pragma unroll
        for (int k16 = 0; k16 < 2; k16++) {
            const int kk2 = k16 * 8;
            uint32_t a[4][4];
#pragma unroll
            for (int mi = 0; mi < 4; mi++) {
                const int mr = wm * 64 + mi * 16 + q;
                a[mi][0] = As[mr * AP2 + kk2 + r2];
                a[mi][1] = As[(mr + 8) * AP2 + kk2 + r2];
                a[mi][2] = As[mr * AP2 + kk2 + r2 + 4];
                a[mi][3] = As[(mr + 8) * AP2 + kk2 + r2 + 4];
            }
#pragma unroll
            for (int ni = 0; ni < 4; ni++) {
                const int nc = wn * 32 + ni * 8 + q;
                uint32_t b[2] = { Bs[nc * BP2 + kk2 + r2], Bs[nc * BP2 + kk2 + r2 + 4] };
#pragma unroll
                for (int mi = 0; mi < 4; mi++)
                    mma_f16(acc[mi][ni], a[mi], b);
            }
        }
        CP_COMMIT();
    }

    const int rb = m0 + wm * 64;
#pragma unroll
    for (int mi = 0; mi < 4; mi++) {
        const int r0 = rb + mi * 16 + q;
#pragma unroll
        for (int ni = 0; ni < 4; ni++) {
            const int col = d0 + wn * 32 + ni * 8 + r2 * 2;
            float* p0 = g_Y + ((size_t)(e * T_TOK) + r0) * DM + col;
            float* p1 = p0 + (size_t)8 * DM;
            float2 v0, v1;
            v0.x = acc[mi][ni][0]; v0.y = acc[mi][ni][1];
            v1.x = acc[mi][ni][2]; v1.y = acc[mi][ni][3];
            *(float2*)p0 = v0;
            *(float2*)p1 = v1;
        }
    }
}

__global__ void combine_kernel(float* __restrict__ out) {
    const int i = blockIdx.x * blockDim.x + threadIdx.x;
    const int t = i / (DM / 4), c = i % (DM / 4);
    const int s0 = g_slot[t * KM + 0], s1 = g_slot[t * KM + 1];
    const float w0 = g_gate[s0], w1 = g_gate[s1];
    const float4 y0 = *((const float4*)g_Y + (size_t)s0 * (DM / 4) + c);
    const float4 y1 = *((const float4*)g_Y + (size_t)s1 * (DM / 4) + c);
    float4 o;
    o.x = w0 * y0.x + w1 * y1.x; o.y = w0 * y0.y + w1 * y1.y;
    o.z = w0 * y0.z + w1 * y1.z; o.w = w0 * y0.w + w1 * y1.w;
    *((float4*)out + i) = o;
}

// ---------------- launch ------------------------------------------------------
extern "C" void kernel_launch(void* const* d_in, const int* in_sizes, int n_in,
                              void* d_out, int out_size) {
    const float* x  = (const float*)d_in[0];
    const float* Wr = (const float*)d_in[1];
    const float* Wg = (const float*)d_in[2];
    const float* Wu = (const float*)d_in[3];
    const float* Wd = (const float*)d_in[4];
    float* out = (float*)d_out;

    cudaFuncSetAttribute(gemm1_kernel, cudaFuncAttributeMaxDynamicSharedMemorySize, G1_SMEM);
    cudaFuncSetAttribute(gemm2_kernel, cudaFuncAttributeMaxDynamicSharedMemorySize, G2_SMEM);

    init_counts_kernel<<<1, 32>>>();
    cvt_x_kernel<<<T_TOK * DM / 4 / 256, 256>>>(x);
    transpose_cvt_kernel<<<dim3(FM / 32, DM / 32, EM), dim3(32, 8)>>>(Wg, 0, DM, FM);
    transpose_cvt_kernel<<<dim3(FM / 32, DM / 32, EM), dim3(32, 8)>>>(Wu, 1, DM, FM);
    transpose_cvt_kernel<<<dim3(DM / 32, FM / 32, EM), dim3(32, 8)>>>(Wd, 2, FM, DM);
    router_kernel<<<T_TOK, 128>>>(x, Wr);
    gemm1_kernel<<<dim3(T_TOK / 128, FM / 64, EM), 256, G1_SMEM>>>();
    gemm2_kernel<<<dim3(T_TOK / 128, DM / 128, EM), 256, G2_SMEM>>>();
    combine_kernel<<<(T_TOK * DM / 4) / 256, 256>>>(out);
}

// round 11
// speedup vs baseline: 1.8583x; 1.8583x over previous
#include <cuda_runtime.h>
#include <cuda_fp16.h>
#include <mma.h>
#include <cstdint>
#include <math.h>

using namespace nvcuda;

#define T_TOK 2048
#define DM    2048
#define FM    8192
#define EM    4
#define KM    2

// ---------------- scratch ----------------------------------------------------
__device__ int    g_count[EM];
__device__ int    g_bucket[EM * T_TOK];
__device__ float  g_gate[EM * T_TOK];
__device__ int    g_slot[T_TOK * KM];
__device__ __half g_xh[T_TOK * DM];                  // x half, [t][d]
__device__ __half g_Wgh[(size_t)EM * DM * FM];       // Wg half, natural [e][d][f]
__device__ __half g_Wuh[(size_t)EM * DM * FM];       // Wu half, natural [e][d][f]
__device__ __half g_Wdh[(size_t)EM * FM * DM];       // Wd half, natural [e][f][d]
__device__ __half g_Hh[(size_t)EM * T_TOK * FM];     // hidden half, [slot][f]
__device__ float  g_Y[(size_t)EM * T_TOK * DM];      // per-slot output fp32

// ---------------- helpers ----------------------------------------------------
__device__ __forceinline__ float silu_f(float x) { return x / (1.0f + expf(-x)); }

__device__ __forceinline__ uint32_t smem_u32(const void* p) {
    uint32_t a;
    asm("{ .reg .u64 t; cvta.to.shared.u64 t, %1; cvt.u32.u64 %0, t; }" : "=r"(a) : "l"(p));
    return a;
}

__device__ __forceinline__ void cpa16(uint32_t dst, const void* src, uint32_t sz) {
    asm volatile("cp.async.cg.shared.global [%0], [%1], 16, %2;\n"
                 :: "r"(dst), "l"(src), "r"(sz));
}
#define CP_COMMIT() asm volatile("cp.async.commit_group;\n" ::: "memory")
#define CP_WAIT1()  asm volatile("cp.async.wait_group 1;\n" ::: "memory")

// ---------------- prep kernels ------------------------------------------------
__global__ void init_counts_kernel() { if (threadIdx.x < EM) g_count[threadIdx.x] = 0; }

__global__ void cvt_x_kernel(const float* __restrict__ x) {
    const int i = blockIdx.x * 256 + threadIdx.x;      // float4 index
    float4 v = ((const float4*)x)[i];
    __half2 h0 = __floats2half2_rn(v.x, v.y);
    __half2 h1 = __floats2half2_rn(v.z, v.w);
    uint2 o;
    o.x = *(uint32_t*)&h0; o.y = *(uint32_t*)&h1;
    ((uint2*)g_xh)[i] = o;
}

// streaming fp32 -> fp16, layout preserved.
// which: 0 -> g_Wgh, 1 -> g_Wuh, 2 -> g_Wdh   (resolved in DEVICE code —
// passing a __device__ symbol from host was the r7/r8 bug)
__global__ void cvt_w_kernel(const float* __restrict__ src, int which) {
    __half* dst = (which == 0) ? g_Wgh : (which == 1) ? g_Wuh : g_Wdh;
    const size_t i = (size_t)blockIdx.x * 256 + threadIdx.x;   // float4 index
    float4 v = ((const float4*)src)[i];
    __half2 h0 = __floats2half2_rn(v.x, v.y);
    __half2 h1 = __floats2half2_rn(v.z, v.w);
    uint2 o;
    o.x = *(uint32_t*)&h0; o.y = *(uint32_t*)&h1;
    ((uint2*)dst)[i] = o;
}

__global__ void router_kernel(const float* __restrict__ x, const float* __restrict__ Wr) {
    const int t = blockIdx.x, tid = threadIdx.x;
    const float* xr = x + (size_t)t * DM;
    float acc[EM] = {0.f, 0.f, 0.f, 0.f};
    for (int d = tid; d < DM; d += 128) {
        const float xv = xr[d];
#pragma unroll
        for (int e = 0; e < EM; e++) acc[e] += xv * Wr[d * EM + e];
    }
    __shared__ float sred[EM][128];
#pragma unroll
    for (int e = 0; e < EM; e++) sred[e][tid] = acc[e];
    __syncthreads();
    for (int s = 64; s > 0; s >>= 1) {
        if (tid < s) {
#pragma unroll
            for (int e = 0; e < EM; e++) sred[e][tid] += sred[e][tid + s];
        }
        __syncthreads();
    }
    if (tid == 0) {
        float l[EM];
#pragma unroll
        for (int e = 0; e < EM; e++) l[e] = sred[e][0];
        float mx = l[0];
#pragma unroll
        for (int e = 1; e < EM; e++) mx = fmaxf(mx, l[e]);
        float p[EM], sum = 0.f;
#pragma unroll
        for (int e = 0; e < EM; e++) { p[e] = expf(l[e] - mx); sum += p[e]; }
        const float inv = 1.0f / sum;
#pragma unroll
        for (int e = 0; e < EM; e++) p[e] *= inv;
        int e0 = 0;
#pragma unroll
        for (int e = 1; e < EM; e++) if (p[e] > p[e0]) e0 = e;
        int e1 = -1;
#pragma unroll
        for (int e = 0; e < EM; e++) {
            if (e == e0) continue;
            if (e1 < 0 || p[e] > p[e1]) e1 = e;
        }
        int s0 = atomicAdd(&g_count[e0], 1);
        g_bucket[e0 * T_TOK + s0] = t; g_gate[e0 * T_TOK + s0] = p[e0];
        g_slot[t * KM + 0] = e0 * T_TOK + s0;
        int s1 = atomicAdd(&g_count[e1], 1);
        g_bucket[e1 * T_TOK + s1] = t; g_gate[e1 * T_TOK + s1] = p[e1];
        g_slot[t * KM + 1] = e1 * T_TOK + s1;
    }
}

// =============== GEMM1: H = silu(x Wg) * (x Wu), wmma =========================
// Block 128M x 64F dual. 8 warps: wm=warp&3 (4x32M), wn=warp>>2 (2x32F).
// A smem [128 m][32 k] pitch 40 halves; Bg/Bu smem [32 k][64 n] pitch 72 halves.
#define G1_AP 40
#define G1_BPn 72
#define G1_AB (128 * G1_AP * 2)            // 10240
#define G1_BB (32 * G1_BPn * 2)            // 4608
#define G1_STAGE (G1_AB + 2 * G1_BB)       // 19456
#define G1_ROWS  65536                     // rows array after float staging region
#define G1_SMEM  (G1_ROWS + 512)

__global__ __launch_bounds__(256, 2)
void gemm1_kernel() {
    extern __shared__ char sm[];
    const int e   = blockIdx.z;
    const int cnt = g_count[e];
    const int m0  = blockIdx.x * 128;
    if (m0 >= cnt) return;
    const int f0  = blockIdx.y * 64;

    const int tid = threadIdx.x, warp = tid >> 5;
    const int wm = warp & 3, wn = warp >> 2;
    const uint32_t sb = smem_u32(sm);
    int* rows = (int*)(sm + G1_ROWS);

    if (tid < 128) {
        const int m = m0 + tid;
        rows[tid] = (m < cnt) ? g_bucket[e * T_TOK + m] : -1;
    }
    __syncthreads();

    const __half* Wge = g_Wgh + (size_t)e * DM * FM + f0;   // [d][f] natural
    const __half* Wue = g_Wuh + (size_t)e * DM * FM + f0;

    auto load_tile = [&](int s, int kt) {
        const int k0 = kt * 32;
        const uint32_t ab = sb + s * G1_STAGE;
#pragma unroll
        for (int p = 0; p < 2; p++) {                  // A: 128 rows x 4 chunks
            const int idx = tid + p * 256;
            const int rr = idx >> 2, c = idx & 3;
            const int tok = rows[rr];
            const __half* src = (tok >= 0) ? (g_xh + (size_t)tok * DM + k0 + c * 8) : g_xh;
            cpa16(ab + rr * (G1_AP * 2) + c * 16, src, (tok >= 0) ? 16u : 0u);
        }
        {   // Bg: 32 k-rows x 8 chunks (128B/row)
            const int kr = tid >> 3, c = tid & 7;
            cpa16(ab + G1_AB + kr * (G1_BPn * 2) + c * 16,
                  Wge + (size_t)(k0 + kr) * FM + c * 8, 16);
        }
        {   // Bu
            const int kr = tid >> 3, c = tid & 7;
            cpa16(ab + G1_AB + G1_BB + kr * (G1_BPn * 2) + c * 16,
                  Wue + (size_t)(k0 + kr) * FM + c * 8, 16);
        }
    };

    wmma::fragment<wmma::accumulator, 16, 16, 16, float> cG[2][2], cU[2][2];
#pragma unroll
    for (int mi = 0; mi < 2; mi++)
#pragma unroll
        for (int ni = 0; ni < 2; ni++) {
            wmma::fill_fragment(cG[mi][ni], 0.0f);
            wmma::fill_fragment(cU[mi][ni], 0.0f);
        }

    const int KT = DM / 32;   // 64
    load_tile(0, 0); CP_COMMIT();
    load_tile(1, 1); CP_COMMIT();

    for (int kt = 0; kt < KT; kt++) {
        CP_WAIT1();
        __syncthreads();
        if (kt + 2 < KT) load_tile((kt + 2) % 3, kt + 2);

        const __half* As = (const __half*)(sm + (kt % 3) * G1_STAGE);
        const __half* Bg = As + 128 * G1_AP;
        const __half* Bu = Bg + 32 * G1_BPn;

#pragma unroll
        for (int ks = 0; ks < 2; ks++) {
            wmma::fragment<wmma::matrix_b, 16, 16, 16, __half, wmma::row_major> fbG[2], fbU[2];
#pragma unroll
            for (int ni = 0; ni < 2; ni++) {
                wmma::load_matrix_sync(fbG[ni], Bg + ks * 16 * G1_BPn + wn * 32 + ni * 16, G1_BPn);
                wmma::load_matrix_sync(fbU[ni], Bu + ks * 16 * G1_BPn + wn * 32 + ni * 16, G1_BPn);
            }
#pragma unroll
            for (int mi = 0; mi < 2; mi++) {
                wmma::fragment<wmma::matrix_a, 16, 16, 16, __half, wmma::row_major> fa;
                wmma::load_matrix_sync(fa, As + (wm * 32 + mi * 16) * G1_AP + ks * 16, G1_AP);
#pragma unroll
                for (int ni = 0; ni < 2; ni++) {
                    wmma::mma_sync(cG[mi][ni], fa, fbG[ni], cG[mi][ni]);
                    wmma::mma_sync(cU[mi][ni], fa, fbU[ni], cU[mi][ni]);
                }
            }
        }
        CP_COMMIT();
    }

    // epilogue: stage accs to smem (reuse pipeline memory), fuse silu, write half H
    __syncthreads();
    float* sg = (float*)sm;                 // 128x64 floats = 32KB
    float* su = sg + 128 * 64;              // next 32KB
#pragma unroll
    for (int mi = 0; mi < 2; mi++)
#pragma unroll
        for (int ni = 0; ni < 2; ni++) {
            const int r = wm * 32 + mi * 16, c = wn * 32 + ni * 16;
            wmma::store_matrix_sync(sg + r * 64 + c, cG[mi][ni], 64, wmma::mem_row_major);
            wmma::store_matrix_sync(su + r * 64 + c, cU[mi][ni], 64, wmma::mem_row_major);
        }
    __syncthreads();
    for (int i = tid; i < 128 * 64; i += 256) {
        const int r = i >> 6, c = i & 63;
        const float g = sg[i], u = su[i];
        g_Hh[((size_t)(e * T_TOK) + m0 + r) * FM + f0 + c] = __float2half_rn(silu_f(g) * u);
    }
}

// =============== GEMM2: Y = H Wd, wmma ========================================
// Block 128M x 128N. 8 warps: wm=warp&1 (2x64M), wn=warp>>1 (4x32N).
// A smem [128 m][32 k] pitch 40; B smem [32 k][128 n] pitch 136.
#define G2_AP 40
#define G2_BPn 136
#define G2_AB (128 * G2_AP * 2)             // 10240
#define G2_BB (32 * G2_BPn * 2)             // 8704
#define G2_STAGE (G2_AB + G2_BB)            // 18944
#define G2_SMEM  (3 * G2_STAGE)             // 56832

__global__ __launch_bounds__(256, 2)
void gemm2_kernel() {
    extern __shared__ char sm[];
    const int e   = blockIdx.z;
    const int cnt = g_count[e];
    const int m0  = blockIdx.x * 128;
    if (m0 >= cnt) return;
    const int d0  = blockIdx.y * 128;

    const int tid = threadIdx.x, warp = tid >> 5;
    const int wm = warp & 1, wn = warp >> 1;
    const uint32_t sb = smem_u32(sm);

    const __half* Hb  = g_Hh + (size_t)(e * T_TOK + m0) * FM;
    const __half* Wde = g_Wdh + (size_t)e * FM * DM + d0;    // [f][d] natural

    auto load_tile = [&](int s, int kt) {
        const int k0 = kt * 32;
        const uint32_t ab = sb + s * G2_STAGE;
#pragma unroll
        for (int p = 0; p < 2; p++) {                  // A: 512 chunks
            const int idx = tid + p * 256;
            const int rr = idx >> 2, c = idx & 3;
            cpa16(ab + rr * (G2_AP * 2) + c * 16, Hb + (size_t)rr * FM + k0 + c * 8, 16);
        }
#pragma unroll
        for (int p = 0; p < 2; p++) {                  // B: 32 rows x 16 chunks
            const int idx = tid + p * 256;
            const int kr = idx >> 4, c = idx & 15;
            cpa16(ab + G2_AB + kr * (G2_BPn * 2) + c * 16,
                  Wde + (size_t)(k0 + kr) * DM + c * 8, 16);
        }
    };

    wmma::fragment<wmma::accumulator, 16, 16, 16, float> cY[4][2];
#pragma unroll
    for (int mi = 0; mi < 4; mi++)
#pragma unroll
        for (int ni = 0; ni < 2; ni++)
            wmma::fill_fragment(cY[mi][ni], 0.0f);

    const int KT = FM / 32;   // 256
    load_tile(0, 0); CP_COMMIT();
    load_tile(1, 1); CP_COMMIT();

    for (int kt = 0; kt < KT; kt++) {
        CP_WAIT1();
        __syncthreads();
        if (kt + 2 < KT) load_tile((kt + 2) % 3, kt + 2);

        const __half* As = (const __half*)(sm + (kt % 3) * G2_STAGE);
        const __half* Bs = As + 128 * G2_AP;

#pragma unroll
        for (int ks = 0; ks < 2; ks++) {
            wmma::fragment<wmma::matrix_b, 16, 16, 16, __half, wmma::row_major> fb[2];
#pragma unroll
            for (int ni = 0; ni < 2; ni++)
                wmma::load_matrix_sync(fb[ni], Bs + ks * 16 * G2_BPn + wn * 32 + ni * 16, G2_BPn);
#pragma unroll
            for (int mi = 0; mi < 4; mi++) {
                wmma::fragment<wmma::matrix_a, 16, 16, 16, __half, wmma::row_major> fa;
                wmma::load_matrix_sync(fa, As + (wm * 64 + mi * 16) * G2_AP + ks * 16, G2_AP);
#pragma unroll
                for (int ni = 0; ni < 2; ni++)
                    wmma::mma_sync(cY[mi][ni], fa, fb[ni], cY[mi][ni]);
            }
        }
        CP_COMMIT();
    }

    // direct gmem store (fp32, ldm = DM)
#pragma unroll
    for (int mi = 0; mi < 4; mi++)
#pragma unroll
        for (int ni = 0; ni < 2; ni++) {
            float* dst = g_Y + ((size_t)(e * T_TOK) + m0 + wm * 64 + mi * 16) * DM
                             + d0 + wn * 32 + ni * 16;
            wmma::store_matrix_sync(dst, cY[mi][ni], DM, wmma::mem_row_major);
        }
}

__global__ void combine_kernel(float* __restrict__ out) {
    const int i = blockIdx.x * blockDim.x + threadIdx.x;
    const int t = i / (DM / 4), c = i % (DM / 4);
    const int s0 = g_slot[t * KM + 0], s1 = g_slot[t * KM + 1];
    const float w0 = g_gate[s0], w1 = g_gate[s1];
    const float4 y0 = *((const float4*)g_Y + (size_t)s0 * (DM / 4) + c);
    const float4 y1 = *((const float4*)g_Y + (size_t)s1 * (DM / 4) + c);
    float4 o;
    o.x = w0 * y0.x + w1 * y1.x; o.y = w0 * y0.y + w1 * y1.y;
    o.z = w0 * y0.z + w1 * y1.z; o.w = w0 * y0.w + w1 * y1.w;
    *((float4*)out + i) = o;
}

// ---------------- launch ------------------------------------------------------
extern "C" void kernel_launch(void* const* d_in, const int* in_sizes, int n_in,
                              void* d_out, int out_size) {
    const float* x  = (const float*)d_in[0];
    const float* Wr = (const float*)d_in[1];
    const float* Wg = (const float*)d_in[2];
    const float* Wu = (const float*)d_in[3];
    const float* Wd = (const float*)d_in[4];
    float* out = (float*)d_out;

    cudaFuncSetAttribute(gemm1_kernel, cudaFuncAttributeMaxDynamicSharedMemorySize, G1_SMEM);
    cudaFuncSetAttribute(gemm2_kernel, cudaFuncAttributeMaxDynamicSharedMemorySize, G2_SMEM);

    const int WQ = (EM * DM * FM) / 4 / 256;     // blocks per weight convert
    init_counts_kernel<<<1, 32>>>();
    cvt_x_kernel<<<T_TOK * DM / 4 / 256, 256>>>(x);
    cvt_w_kernel<<<WQ, 256>>>(Wg, 0);
    cvt_w_kernel<<<WQ, 256>>>(Wu, 1);
    cvt_w_kernel<<<WQ, 256>>>(Wd, 2);
    router_kernel<<<T_TOK, 128>>>(x, Wr);
    gemm1_kernel<<<dim3(T_TOK / 128, FM / 64, EM), 256, G1_SMEM>>>();
    gemm2_kernel<<<dim3(T_TOK / 128, DM / 128, EM), 256, G2_SMEM>>>();
    combine_kernel<<<(T_TOK * DM / 4) / 256, 256>>>(out);
}